// round 5
// baseline (speedup 1.0000x reference)
#include <cuda_runtime.h>
#include <math.h>

#define Hh 240
#define Ww 1216
#define Bb 4
#define HW (Hh*Ww)
#define PH 244
#define PW 1220
#define PHW (PH*PW)

// Tap table: one u64 per (pixel, tap):
//   bits [0:19)  padded linear index (y0+2)*PW + (x0+2)
//   bits [19:31) wy unorm12, [31:43) wx unorm12
//   bits [43:64) aff, signed fixed-point 2^-18
__device__ __align__(32) unsigned long long g_tab[Bb*9*HW];
// Pair-format padded ping-pong feat buffers: pair[p] = (f[p], f[p+1]).
// Zero-initialized; border cells are NEVER written -> clamped taps read zeros.
__device__ float2 g_pa[Bb*PHW];
__device__ float2 g_pb[Bb*PHW];

__device__ __forceinline__ unsigned long long pack2f(float a, float b){
    float2 t = make_float2(a, b);
    return *reinterpret_cast<unsigned long long*>(&t);
}
__device__ __forceinline__ float2 unpack2f(unsigned long long v){
    return *reinterpret_cast<float2*>(&v);
}

__device__ __forceinline__ float bilin_conf(const float* __restrict__ img, float sy, float sx)
{
    float fy = floorf(sy), fx = floorf(sx);
    float wy = sy - fy,  wx = sx - fx;
    int y0 = (int)fy, x0 = (int)fx;
    int y1 = y0 + 1, x1 = x0 + 1;
    float v00=0.f, v01=0.f, v10=0.f, v11=0.f;
    bool by0 = (unsigned)y0 < Hh, by1 = (unsigned)y1 < Hh;
    bool bx0 = (unsigned)x0 < Ww, bx1 = (unsigned)x1 < Ww;
    if (by0 && bx0) v00 = __ldg(img + y0*Ww + x0);
    if (by0 && bx1) v01 = __ldg(img + y0*Ww + x1);
    if (by1 && bx0) v10 = __ldg(img + y1*Ww + x0);
    if (by1 && bx1) v11 = __ldg(img + y1*Ww + x1);
    return (1.f-wy)*((1.f-wx)*v00 + wx*v01) + wy*((1.f-wx)*v10 + wx*v11);
}

__device__ __forceinline__ void post_pixel(const float acc[24], int b, int y, int xi,
    const float* __restrict__ cb, float iasc,
    float* __restrict__ out_off, float* __restrict__ out_aff)
{
    int pi = y*Ww + xi;

    float offy[9], offx[9];
    #pragma unroll
    for (int m=0;m<9;m++){
        offy[m] = (m<4) ? acc[2*m]   : ((m==4) ? 0.f : acc[2*(m-1)]);
        offx[m] = (m<4) ? acc[2*m+1] : ((m==4) ? 0.f : acc[2*(m-1)+1]);
    }

    float a8[8], ssum = 0.f;
    #pragma unroll
    for (int k=0;k<8;k++){
        float av = tanhf(acc[16+k]) * iasc;
        av *= bilin_conf(cb, (float)y + acc[2*k], (float)xi + acc[2*k+1]);
        a8[k] = av;
        ssum += fabsf(av);
    }
    float s = ssum + 1e-4f;
    if (s < 1.f) s = 1.f;
    float inv = 1.0f / s;
    float asum = 0.f;
    #pragma unroll
    for (int k=0;k<8;k++){ a8[k] *= inv; asum += a8[k]; }
    float aref = 1.f - asum;

    float affv[9];
    #pragma unroll
    for (int m=0;m<9;m++) affv[m] = (m<4) ? a8[m] : ((m==4) ? aref : a8[m-1]);

    // plain stores (the __stcs variant measured +70us on the conv kernel)
    #pragma unroll
    for (int m=0;m<9;m++){
        out_off[((size_t)b*18 + 2*m    )*HW + pi] = offy[m];
        out_off[((size_t)b*18 + 2*m + 1)*HW + pi] = offx[m];
        out_aff[((size_t)b*9  + m      )*HW + pi] = affv[m];
    }

    // encode tap table
    #pragma unroll
    for (int m=0;m<9;m++){
        float ty = (float)(y  + m/3 - 1) + offy[m];
        float tx = (float)(xi + m%3 - 1) + offx[m];
        float fy = floorf(ty), fx2 = floorf(tx);
        float wy = ty - fy, wx = tx - fx2;
        int y0 = (int)fy, x0 = (int)fx2;
        if (y0 < -2) y0 = -2;  if (y0 > Hh) y0 = Hh;
        if (x0 < -2) x0 = -2;  if (x0 > Ww) x0 = Ww;
        unsigned idx = (unsigned)((y0+2)*PW + (x0+2));
        unsigned uy = __float2uint_rn(wy * 4095.f);
        unsigned ux = __float2uint_rn(wx * 4095.f);
        int ia = __float2int_rn(affv[m] * 262144.f);
        unsigned long long v =
              ((unsigned long long)((unsigned)ia & 0x1FFFFFu) << 43)
            | ((unsigned long long)ux << 31)
            | ((unsigned long long)uy << 19)
            | (unsigned long long)idx;
        g_tab[(b*9 + m)*HW + pi] = v;
    }
}

// Fused: 3x3 conv (8ch -> 24ch, f32x2 over a 2-pixel pair) + post + init pair feat.
__global__ void __launch_bounds__(256) conv_post_kernel(
    const float* __restrict__ feat_init,
    const float* __restrict__ guidance,
    const float* __restrict__ confidence,
    const float* __restrict__ feat_fix,
    const float* __restrict__ w_oa,
    const float* __restrict__ b_oa,
    const float* __restrict__ ascale,
    float* __restrict__ out)
{
    __shared__ unsigned long long wsh2[1728];   // (w,w) pairs, layout [c][dy][dx][o]
    for (int j = threadIdx.x; j < 1728; j += 256){
        int o = j % 24, r = j / 24;
        float w = __ldg(w_oa + o*72 + r);
        wsh2[j] = pack2f(w, w);
    }
    __syncthreads();

    int t  = blockIdx.x*256 + threadIdx.x;
    int pp = t*2;
    int b  = pp / HW;
    int p  = pp - b*HW;
    int y  = p / Ww;
    int x  = p - y*Ww;                 // pixels (x, x+1), x even

    unsigned long long accp[24];
    #pragma unroll
    for (int o=0;o<24;o++){ float bo = __ldg(b_oa+o); accp[o] = pack2f(bo, bo); }

    const float* gb = guidance + (size_t)b*8*HW;
    #pragma unroll 1
    for (int c=0;c<8;c++){
        #pragma unroll
        for (int dy=0;dy<3;dy++){
            int yy = y + dy - 1;
            if ((unsigned)yy >= Hh) continue;
            const float* grow = gb + c*HW + yy*Ww;
            float gva[4];
            gva[0] = (x >= 1)     ? __ldg(grow + x - 1) : 0.f;
            gva[1] =                __ldg(grow + x);
            gva[2] =                __ldg(grow + x + 1);
            gva[3] = (x + 2 < Ww) ? __ldg(grow + x + 2) : 0.f;
            #pragma unroll
            for (int dx=0;dx<3;dx++){
                unsigned long long ga = pack2f(gva[dx], gva[dx+1]);
                const ulonglong2* wp = (const ulonglong2*)(wsh2 + (c*9 + dy*3 + dx)*24);
                #pragma unroll
                for (int q=0;q<12;q++){
                    ulonglong2 w2 = wp[q];
                    asm("fma.rn.f32x2 %0, %1, %2, %0;" : "+l"(accp[2*q])   : "l"(ga), "l"(w2.x));
                    asm("fma.rn.f32x2 %0, %1, %2, %0;" : "+l"(accp[2*q+1]) : "l"(ga), "l"(w2.y));
                }
            }
        }
    }

    float acc0[24], acc1[24];
    #pragma unroll
    for (int o=0;o<24;o++){ float2 u = unpack2f(accp[o]); acc0[o]=u.x; acc1[o]=u.y; }

    const float* cb  = confidence + (size_t)b*HW;
    const float* fxb = feat_fix   + (size_t)b*HW;
    const float* fib = feat_init  + (size_t)b*HW;
    float iasc = 1.0f / (__ldg(ascale) + 1e-8f);

    float* out_off = out + (size_t)Bb*HW;
    float* out_aff = out + (size_t)Bb*HW*19;

    post_pixel(acc0, b, y, x,   cb, iasc, out_off, out_aff);
    post_pixel(acc1, b, y, x+1, cb, iasc, out_off, out_aff);

    // pre-blended initial feat, pair format: f(p) -> pair[p].x and pair[p-1].y
    float fv0 = __ldg(fxb + p),     fi0 = __ldg(fib + p);
    float fv1 = __ldg(fxb + p + 1), fi1 = __ldg(fib + p + 1);
    float f0 = (fv0 > 0.f) ? fv0 : fi0;
    float f1 = (fv1 > 0.f) ? fv1 : fi1;
    float2* pa = g_pa + (size_t)b*PHW;
    int pidx = (y+2)*PW + (x+2);
    pa[pidx] = make_float2(f0, f1);
    ((float*)(pa + pidx - 1))[1] = f0;   // pair[p-1].y
    ((float*)(pa + pidx + 1))[0] = f1;   // pair[p+1].x
}

// One propagation iteration, 4 pixels per thread.
// Table loads: 32B vectorized with L2::evict_last to pin the 84MB table in L2.
__global__ void __launch_bounds__(256) prop_kernel(
    const float* __restrict__ feat_fix, float* __restrict__ dout, int it)
{
    int t = blockIdx.x*256 + threadIdx.x;   // grid = Bb*HW/4 threads
    int pp = t*4;
    int b = pp / HW;
    int p = pp - b*HW;
    int y = p / Ww;
    int x = p - y*Ww;                       // x % 4 == 0

    const float2* fin = ((it & 1) ? g_pb : g_pa) + (size_t)b*PHW;

    float acc0 = 0.f, acc1 = 0.f, acc2 = 0.f, acc3 = 0.f;
    #pragma unroll
    for (int k=0;k<9;k++){
        unsigned long long v0, v1, v2, v3;
        const unsigned long long* tp = &g_tab[(b*9 + k)*HW + p];   // 32B aligned
        asm("ld.global.nc.L2::evict_last.v4.b64 {%0,%1,%2,%3}, [%4];"
            : "=l"(v0), "=l"(v1), "=l"(v2), "=l"(v3) : "l"(tp));
        #pragma unroll
        for (int i=0;i<4;i++){
            unsigned long long v = (i==0)?v0:(i==1)?v1:(i==2)?v2:v3;
            int idx  = (int)((unsigned)v & 0x7FFFFu);
            float wy = (float)((unsigned)(v >> 19) & 0xFFFu) * (1.f/4095.f);
            float wx = (float)((unsigned)(v >> 31) & 0xFFFu) * (1.f/4095.f);
            float af = (float)((long long)v >> 43) * (1.f/262144.f);
            float2 c0 = __ldg(fin + idx);
            float2 c1 = __ldg(fin + idx + PW);
            float top = c0.x + wx*(c0.y - c0.x);
            float bot = c1.x + wx*(c1.y - c1.x);
            float s = top + wy*(bot - top);
            if      (i==0) acc0 = fmaf(af, s, acc0);
            else if (i==1) acc1 = fmaf(af, s, acc1);
            else if (i==2) acc2 = fmaf(af, s, acc2);
            else           acc3 = fmaf(af, s, acc3);
        }
    }

    float4 fv = __ldg((const float4*)(feat_fix + pp));
    float f0 = (fv.x > 0.f) ? fv.x : acc0;
    float f1 = (fv.y > 0.f) ? fv.y : acc1;
    float f2 = (fv.z > 0.f) ? fv.z : acc2;
    float f3 = (fv.w > 0.f) ? fv.w : acc3;

    if (it != 17){
        float2* fout = ((it & 1) ? g_pa : g_pb) + (size_t)b*PHW;
        int pidx = (y+2)*PW + (x+2);
        // pairs pidx..pidx+2 fully, pidx+3.x, and pidx-1.y (next thread / border fills the rest)
        *reinterpret_cast<float4*>(fout + pidx) = make_float4(f0, f1, f1, f2);
        fout[pidx + 2] = make_float2(f2, f3);
        ((float*)(fout + pidx + 3))[0] = f3;
        ((float*)(fout + pidx - 1))[1] = f0;
    } else {
        *reinterpret_cast<float4*>(dout + pp) = make_float4(acc0, acc1, acc2, acc3);
    }
}

extern "C" void kernel_launch(void* const* d_in, const int* in_sizes, int n_in,
                              void* d_out, int out_size)
{
    const float* feat_init  = (const float*)d_in[0];
    const float* guidance   = (const float*)d_in[1];
    const float* confidence = (const float*)d_in[2];
    const float* feat_fix   = (const float*)d_in[3];
    const float* w_oa       = (const float*)d_in[4];
    const float* b_oa       = (const float*)d_in[5];
    const float* ascale     = (const float*)d_in[6];
    float* out = (float*)d_out;

    (void)in_sizes; (void)n_in; (void)out_size;

    conv_post_kernel<<<(Bb*HW/2)/256, 256>>>(feat_init, guidance, confidence,
                                             feat_fix, w_oa, b_oa, ascale, out);
    for (int it = 0; it < 18; ++it)
        prop_kernel<<<(Bb*HW/4)/256, 256>>>(feat_fix, out, it);
}

// round 6
// speedup vs baseline: 1.1176x; 1.1176x over previous
#include <cuda_runtime.h>
#include <math.h>

#define Hh 240
#define Ww 1216
#define Bb 4
#define HW (Hh*Ww)
#define PH 244
#define PW 1220
#define PHW (PH*PW)

// Tap table: one u64 per (pixel, tap), tap-major for coalescing:
//   bits [0:19)  padded linear index (y0+2)*PW + (x0+2)
//   bits [19:31) wy unorm12, [31:43) wx unorm12
//   bits [43:64) aff, signed fixed-point 2^-18
__device__ unsigned long long g_tab[Bb*9*HW];
// Pair-format padded ping-pong feat buffers: pair[p] = (f[p], f[p+1]).
// Zero-initialized; border cells are NEVER written -> clamped taps read zeros.
__device__ float2 g_pa[Bb*PHW];
__device__ float2 g_pb[Bb*PHW];

__device__ __forceinline__ unsigned long long pack2f(float a, float b){
    float2 t = make_float2(a, b);
    return *reinterpret_cast<unsigned long long*>(&t);
}
__device__ __forceinline__ float2 unpack2f(unsigned long long v){
    return *reinterpret_cast<float2*>(&v);
}

__device__ __forceinline__ float bilin_conf(const float* __restrict__ img, float sy, float sx)
{
    float fy = floorf(sy), fx = floorf(sx);
    float wy = sy - fy,  wx = sx - fx;
    int y0 = (int)fy, x0 = (int)fx;
    int y1 = y0 + 1, x1 = x0 + 1;
    float v00=0.f, v01=0.f, v10=0.f, v11=0.f;
    bool by0 = (unsigned)y0 < Hh, by1 = (unsigned)y1 < Hh;
    bool bx0 = (unsigned)x0 < Ww, bx1 = (unsigned)x1 < Ww;
    if (by0 && bx0) v00 = __ldg(img + y0*Ww + x0);
    if (by0 && bx1) v01 = __ldg(img + y0*Ww + x1);
    if (by1 && bx0) v10 = __ldg(img + y1*Ww + x0);
    if (by1 && bx1) v11 = __ldg(img + y1*Ww + x1);
    return (1.f-wy)*((1.f-wx)*v00 + wx*v01) + wy*((1.f-wx)*v10 + wx*v11);
}

__device__ __forceinline__ void post_pixel(const float acc[24], int b, int y, int xi,
    const float* __restrict__ cb, float iasc,
    float* __restrict__ out_off, float* __restrict__ out_aff)
{
    int pi = y*Ww + xi;

    float offy[9], offx[9];
    #pragma unroll
    for (int m=0;m<9;m++){
        offy[m] = (m<4) ? acc[2*m]   : ((m==4) ? 0.f : acc[2*(m-1)]);
        offx[m] = (m<4) ? acc[2*m+1] : ((m==4) ? 0.f : acc[2*(m-1)+1]);
    }

    float a8[8], ssum = 0.f;
    #pragma unroll
    for (int k=0;k<8;k++){
        float av = tanhf(acc[16+k]) * iasc;
        av *= bilin_conf(cb, (float)y + acc[2*k], (float)xi + acc[2*k+1]);
        a8[k] = av;
        ssum += fabsf(av);
    }
    float s = ssum + 1e-4f;
    if (s < 1.f) s = 1.f;
    float inv = 1.0f / s;
    float asum = 0.f;
    #pragma unroll
    for (int k=0;k<8;k++){ a8[k] *= inv; asum += a8[k]; }
    float aref = 1.f - asum;

    float affv[9];
    #pragma unroll
    for (int m=0;m<9;m++) affv[m] = (m<4) ? a8[m] : ((m==4) ? aref : a8[m-1]);

    // plain stores (measured: __stcs here cost +70us)
    #pragma unroll
    for (int m=0;m<9;m++){
        out_off[((size_t)b*18 + 2*m    )*HW + pi] = offy[m];
        out_off[((size_t)b*18 + 2*m + 1)*HW + pi] = offx[m];
        out_aff[((size_t)b*9  + m      )*HW + pi] = affv[m];
    }

    // encode tap table
    #pragma unroll
    for (int m=0;m<9;m++){
        float ty = (float)(y  + m/3 - 1) + offy[m];
        float tx = (float)(xi + m%3 - 1) + offx[m];
        float fy = floorf(ty), fx2 = floorf(tx);
        float wy = ty - fy, wx = tx - fx2;
        int y0 = (int)fy, x0 = (int)fx2;
        if (y0 < -2) y0 = -2;  if (y0 > Hh) y0 = Hh;
        if (x0 < -2) x0 = -2;  if (x0 > Ww) x0 = Ww;
        unsigned idx = (unsigned)((y0+2)*PW + (x0+2));
        unsigned uy = __float2uint_rn(wy * 4095.f);
        unsigned ux = __float2uint_rn(wx * 4095.f);
        int ia = __float2int_rn(affv[m] * 262144.f);
        unsigned long long v =
              ((unsigned long long)((unsigned)ia & 0x1FFFFFu) << 43)
            | ((unsigned long long)ux << 31)
            | ((unsigned long long)uy << 19)
            | (unsigned long long)idx;
        g_tab[(b*9 + m)*HW + pi] = v;
    }
}

// Fused: 3x3 conv (8ch -> 24ch, f32x2 over a 2-pixel pair) + post + init pair feat.
__global__ void __launch_bounds__(256) conv_post_kernel(
    const float* __restrict__ feat_init,
    const float* __restrict__ guidance,
    const float* __restrict__ confidence,
    const float* __restrict__ feat_fix,
    const float* __restrict__ w_oa,
    const float* __restrict__ b_oa,
    const float* __restrict__ ascale,
    float* __restrict__ out)
{
    __shared__ unsigned long long wsh2[1728];   // (w,w) pairs, layout [c][dy][dx][o]
    for (int j = threadIdx.x; j < 1728; j += 256){
        int o = j % 24, r = j / 24;
        float w = __ldg(w_oa + o*72 + r);
        wsh2[j] = pack2f(w, w);
    }
    __syncthreads();

    int t  = blockIdx.x*256 + threadIdx.x;
    int pp = t*2;
    int b  = pp / HW;
    int p  = pp - b*HW;
    int y  = p / Ww;
    int x  = p - y*Ww;                 // pixels (x, x+1), x even

    unsigned long long accp[24];
    #pragma unroll
    for (int o=0;o<24;o++){ float bo = __ldg(b_oa+o); accp[o] = pack2f(bo, bo); }

    const float* gb = guidance + (size_t)b*8*HW;
    #pragma unroll 1
    for (int c=0;c<8;c++){
        #pragma unroll
        for (int dy=0;dy<3;dy++){
            int yy = y + dy - 1;
            if ((unsigned)yy >= Hh) continue;
            const float* grow = gb + c*HW + yy*Ww;
            float gva[4];
            gva[0] = (x >= 1)     ? __ldg(grow + x - 1) : 0.f;
            gva[1] =                __ldg(grow + x);
            gva[2] =                __ldg(grow + x + 1);
            gva[3] = (x + 2 < Ww) ? __ldg(grow + x + 2) : 0.f;
            #pragma unroll
            for (int dx=0;dx<3;dx++){
                unsigned long long ga = pack2f(gva[dx], gva[dx+1]);
                const ulonglong2* wp = (const ulonglong2*)(wsh2 + (c*9 + dy*3 + dx)*24);
                #pragma unroll
                for (int q=0;q<12;q++){
                    ulonglong2 w2 = wp[q];
                    asm("fma.rn.f32x2 %0, %1, %2, %0;" : "+l"(accp[2*q])   : "l"(ga), "l"(w2.x));
                    asm("fma.rn.f32x2 %0, %1, %2, %0;" : "+l"(accp[2*q+1]) : "l"(ga), "l"(w2.y));
                }
            }
        }
    }

    float acc0[24], acc1[24];
    #pragma unroll
    for (int o=0;o<24;o++){ float2 u = unpack2f(accp[o]); acc0[o]=u.x; acc1[o]=u.y; }

    const float* cb  = confidence + (size_t)b*HW;
    const float* fxb = feat_fix   + (size_t)b*HW;
    const float* fib = feat_init  + (size_t)b*HW;
    float iasc = 1.0f / (__ldg(ascale) + 1e-8f);

    float* out_off = out + (size_t)Bb*HW;
    float* out_aff = out + (size_t)Bb*HW*19;

    post_pixel(acc0, b, y, x,   cb, iasc, out_off, out_aff);
    post_pixel(acc1, b, y, x+1, cb, iasc, out_off, out_aff);

    // pre-blended initial feat, pair format: f(p) -> pair[p].x and pair[p-1].y
    float fv0 = __ldg(fxb + p),     fi0 = __ldg(fib + p);
    float fv1 = __ldg(fxb + p + 1), fi1 = __ldg(fib + p + 1);
    float f0 = (fv0 > 0.f) ? fv0 : fi0;
    float f1 = (fv1 > 0.f) ? fv1 : fi1;
    float2* pa = g_pa + (size_t)b*PHW;
    int pidx = (y+2)*PW + (x+2);
    pa[pidx] = make_float2(f0, f1);
    ((float*)(pa + pidx - 1))[1] = f0;   // pair[p-1].y
    ((float*)(pa + pidx + 1))[0] = f1;   // pair[p+1].x
}

// One propagation iteration, 1 pixel per thread, explicitly MLP-batched:
// phase A: 9 table loads in flight; phase B: 18 corner loads in flight; phase C: math.
__global__ void __launch_bounds__(256, 2) prop_kernel(
    const float* __restrict__ feat_fix, float* __restrict__ dout, int it)
{
    int t = blockIdx.x*256 + threadIdx.x;   // grid = Bb*HW threads
    int b = t / HW;
    int p = t - b*HW;

    const float2* fin = ((it & 1) ? g_pb : g_pa) + (size_t)b*PHW;
    const unsigned long long* tb = g_tab + (size_t)b*9*HW + p;

    // Phase A: all 9 independent table loads
    unsigned long long tw[9];
    #pragma unroll
    for (int k=0;k<9;k++)
        tw[k] = __ldg(tb + k*HW);

    // Phase B: all 18 corner-pair loads
    float2 ca[9], cb9[9];
    #pragma unroll
    for (int k=0;k<9;k++){
        int idx = (int)((unsigned)tw[k] & 0x7FFFFu);
        ca[k]  = __ldg(fin + idx);
        cb9[k] = __ldg(fin + idx + PW);
    }

    // Phase C: decode + bilinear + accumulate
    float acc = 0.f;
    #pragma unroll
    for (int k=0;k<9;k++){
        unsigned long long v = tw[k];
        float wy = (float)((unsigned)(v >> 19) & 0xFFFu) * (1.f/4095.f);
        float wx = (float)((unsigned)(v >> 31) & 0xFFFu) * (1.f/4095.f);
        float af = (float)((long long)v >> 43) * (1.f/262144.f);
        float top = ca[k].x  + wx*(ca[k].y  - ca[k].x);
        float bot = cb9[k].x + wx*(cb9[k].y - cb9[k].x);
        acc = fmaf(af, top + wy*(bot - top), acc);
    }

    if (it != 17){
        float fv = __ldg(feat_fix + t);
        float f  = (fv > 0.f) ? fv : acc;
        float2* fout = ((it & 1) ? g_pa : g_pb) + (size_t)b*PHW;
        int y = p / Ww;
        int x = p - y*Ww;
        int pidx = (y+2)*PW + (x+2);
        ((float*)(fout + pidx    ))[0] = f;   // pair[p].x
        ((float*)(fout + pidx - 1))[1] = f;   // pair[p-1].y
    } else {
        dout[t] = acc;                        // final: raw aggregate
    }
}

extern "C" void kernel_launch(void* const* d_in, const int* in_sizes, int n_in,
                              void* d_out, int out_size)
{
    const float* feat_init  = (const float*)d_in[0];
    const float* guidance   = (const float*)d_in[1];
    const float* confidence = (const float*)d_in[2];
    const float* feat_fix   = (const float*)d_in[3];
    const float* w_oa       = (const float*)d_in[4];
    const float* b_oa       = (const float*)d_in[5];
    const float* ascale     = (const float*)d_in[6];
    float* out = (float*)d_out;

    (void)in_sizes; (void)n_in; (void)out_size;

    conv_post_kernel<<<(Bb*HW/2)/256, 256>>>(feat_init, guidance, confidence,
                                             feat_fix, w_oa, b_oa, ascale, out);
    for (int it = 0; it < 18; ++it)
        prop_kernel<<<(Bb*HW)/256, 256>>>(feat_fix, out, it);
}

// round 7
// speedup vs baseline: 1.3705x; 1.2262x over previous
#include <cuda_runtime.h>
#include <math.h>

#define Hh 240
#define Ww 1216
#define Bb 4
#define HW (Hh*Ww)
#define PH 244
#define PW 1220
#define PHW (PH*PW)

// Tap table: one u64 per (pixel, tap), tap-major:
//   bits [0:19)  padded linear index (y0+2)*PW + (x0+2)
//   bits [19:31) wy unorm12, [31:43) wx unorm12
//   bits [43:64) aff, signed fixed-point 2^-18
__device__ unsigned long long g_tab[Bb*9*HW];
// Pair-format padded ping-pong feat buffers: pair[q] = (f_pad[q], f_pad[q+1]).
// Zero-initialized; border elements are never written -> clamped taps read zeros.
__device__ float2 g_pa[Bb*PHW];
__device__ float2 g_pb[Bb*PHW];

__device__ __forceinline__ unsigned long long pack2f(float a, float b){
    float2 t = make_float2(a, b);
    return *reinterpret_cast<unsigned long long*>(&t);
}
__device__ __forceinline__ float2 unpack2f(unsigned long long v){
    return *reinterpret_cast<float2*>(&v);
}

__device__ __forceinline__ float bilin_conf(const float* __restrict__ img, float sy, float sx)
{
    float fy = floorf(sy), fx = floorf(sx);
    float wy = sy - fy,  wx = sx - fx;
    int y0 = (int)fy, x0 = (int)fx;
    int y1 = y0 + 1, x1 = x0 + 1;
    float v00=0.f, v01=0.f, v10=0.f, v11=0.f;
    bool by0 = (unsigned)y0 < Hh, by1 = (unsigned)y1 < Hh;
    bool bx0 = (unsigned)x0 < Ww, bx1 = (unsigned)x1 < Ww;
    if (by0 && bx0) v00 = __ldg(img + y0*Ww + x0);
    if (by0 && bx1) v01 = __ldg(img + y0*Ww + x1);
    if (by1 && bx0) v10 = __ldg(img + y1*Ww + x0);
    if (by1 && bx1) v11 = __ldg(img + y1*Ww + x1);
    return (1.f-wy)*((1.f-wx)*v00 + wx*v01) + wy*((1.f-wx)*v10 + wx*v11);
}

__device__ __forceinline__ void post_pixel(const float acc[24], int b, int y, int xi,
    const float* __restrict__ cb, float iasc,
    float* __restrict__ out_off, float* __restrict__ out_aff)
{
    int pi = y*Ww + xi;

    float offy[9], offx[9];
    #pragma unroll
    for (int m=0;m<9;m++){
        offy[m] = (m<4) ? acc[2*m]   : ((m==4) ? 0.f : acc[2*(m-1)]);
        offx[m] = (m<4) ? acc[2*m+1] : ((m==4) ? 0.f : acc[2*(m-1)+1]);
    }

    float a8[8], ssum = 0.f;
    #pragma unroll
    for (int k=0;k<8;k++){
        float av = tanhf(acc[16+k]) * iasc;
        av *= bilin_conf(cb, (float)y + acc[2*k], (float)xi + acc[2*k+1]);
        a8[k] = av;
        ssum += fabsf(av);
    }
    float s = ssum + 1e-4f;
    if (s < 1.f) s = 1.f;
    float inv = 1.0f / s;
    float asum = 0.f;
    #pragma unroll
    for (int k=0;k<8;k++){ a8[k] *= inv; asum += a8[k]; }
    float aref = 1.f - asum;

    float affv[9];
    #pragma unroll
    for (int m=0;m<9;m++) affv[m] = (m<4) ? a8[m] : ((m==4) ? aref : a8[m-1]);

    // plain stores (measured: __stcs here cost +70us)
    #pragma unroll
    for (int m=0;m<9;m++){
        out_off[((size_t)b*18 + 2*m    )*HW + pi] = offy[m];
        out_off[((size_t)b*18 + 2*m + 1)*HW + pi] = offx[m];
        out_aff[((size_t)b*9  + m      )*HW + pi] = affv[m];
    }

    // encode tap table
    #pragma unroll
    for (int m=0;m<9;m++){
        float ty = (float)(y  + m/3 - 1) + offy[m];
        float tx = (float)(xi + m%3 - 1) + offx[m];
        float fy = floorf(ty), fx2 = floorf(tx);
        float wy = ty - fy, wx = tx - fx2;
        int y0 = (int)fy, x0 = (int)fx2;
        if (y0 < -2) y0 = -2;  if (y0 > Hh) y0 = Hh;
        if (x0 < -2) x0 = -2;  if (x0 > Ww) x0 = Ww;
        unsigned idx = (unsigned)((y0+2)*PW + (x0+2));
        unsigned uy = __float2uint_rn(wy * 4095.f);
        unsigned ux = __float2uint_rn(wx * 4095.f);
        int ia = __float2int_rn(affv[m] * 262144.f);
        unsigned long long v =
              ((unsigned long long)((unsigned)ia & 0x1FFFFFu) << 43)
            | ((unsigned long long)ux << 31)
            | ((unsigned long long)uy << 19)
            | (unsigned long long)idx;
        g_tab[(b*9 + m)*HW + pi] = v;
    }
}

// Fused: 3x3 conv (8ch -> 24ch, f32x2 over a 2-pixel pair) + post + init pair feat.
__global__ void __launch_bounds__(256) conv_post_kernel(
    const float* __restrict__ feat_init,
    const float* __restrict__ guidance,
    const float* __restrict__ confidence,
    const float* __restrict__ feat_fix,
    const float* __restrict__ w_oa,
    const float* __restrict__ b_oa,
    const float* __restrict__ ascale,
    float* __restrict__ out)
{
    __shared__ unsigned long long wsh2[1728];   // (w,w) pairs, layout [c][dy][dx][o]
    for (int j = threadIdx.x; j < 1728; j += 256){
        int o = j % 24, r = j / 24;
        float w = __ldg(w_oa + o*72 + r);
        wsh2[j] = pack2f(w, w);
    }
    __syncthreads();

    int t  = blockIdx.x*256 + threadIdx.x;
    int pp = t*2;
    int b  = pp / HW;
    int p  = pp - b*HW;
    int y  = p / Ww;
    int x  = p - y*Ww;                 // pixels (x, x+1), x even

    unsigned long long accp[24];
    #pragma unroll
    for (int o=0;o<24;o++){ float bo = __ldg(b_oa+o); accp[o] = pack2f(bo, bo); }

    const float* gb = guidance + (size_t)b*8*HW;
    #pragma unroll 1
    for (int c=0;c<8;c++){
        #pragma unroll
        for (int dy=0;dy<3;dy++){
            int yy = y + dy - 1;
            if ((unsigned)yy >= Hh) continue;
            const float* grow = gb + c*HW + yy*Ww;
            float gva[4];
            gva[0] = (x >= 1)     ? __ldg(grow + x - 1) : 0.f;
            gva[1] =                __ldg(grow + x);
            gva[2] =                __ldg(grow + x + 1);
            gva[3] = (x + 2 < Ww) ? __ldg(grow + x + 2) : 0.f;
            #pragma unroll
            for (int dx=0;dx<3;dx++){
                unsigned long long ga = pack2f(gva[dx], gva[dx+1]);
                const ulonglong2* wp = (const ulonglong2*)(wsh2 + (c*9 + dy*3 + dx)*24);
                #pragma unroll
                for (int q=0;q<12;q++){
                    ulonglong2 w2 = wp[q];
                    asm("fma.rn.f32x2 %0, %1, %2, %0;" : "+l"(accp[2*q])   : "l"(ga), "l"(w2.x));
                    asm("fma.rn.f32x2 %0, %1, %2, %0;" : "+l"(accp[2*q+1]) : "l"(ga), "l"(w2.y));
                }
            }
        }
    }

    float acc0[24], acc1[24];
    #pragma unroll
    for (int o=0;o<24;o++){ float2 u = unpack2f(accp[o]); acc0[o]=u.x; acc1[o]=u.y; }

    const float* cb  = confidence + (size_t)b*HW;
    const float* fxb = feat_fix   + (size_t)b*HW;
    const float* fib = feat_init  + (size_t)b*HW;
    float iasc = 1.0f / (__ldg(ascale) + 1e-8f);

    float* out_off = out + (size_t)Bb*HW;
    float* out_aff = out + (size_t)Bb*HW*19;

    post_pixel(acc0, b, y, x,   cb, iasc, out_off, out_aff);
    post_pixel(acc1, b, y, x+1, cb, iasc, out_off, out_aff);

    // pre-blended initial feat, pair format: f(p) -> pair[p].x and pair[p-1].y
    float fv0 = __ldg(fxb + p),     fi0 = __ldg(fib + p);
    float fv1 = __ldg(fxb + p + 1), fi1 = __ldg(fib + p + 1);
    float f0 = (fv0 > 0.f) ? fv0 : fi0;
    float f1 = (fv1 > 0.f) ? fv1 : fi1;
    float2* pa = g_pa + (size_t)b*PHW;
    int pidx = (y+2)*PW + (x+2);
    pa[pidx] = make_float2(f0, f1);
    ((float*)(pa + pidx - 1))[1] = f0;   // pair[p-1].y
    ((float*)(pa + pidx + 1))[0] = f1;   // pair[p+1].x
}

// One propagation iteration for a 2-batch group (L2-resident table working set).
// 1 pixel/thread, simple loop (ptxas pipelines at low reg count -> occ ~87%).
__global__ void __launch_bounds__(256) prop_kernel(
    const float* __restrict__ feat_fix, float* __restrict__ dout, int it, int b0)
{
    int t  = blockIdx.x*256 + threadIdx.x;   // grid = 2*HW threads
    int b  = b0 + t / HW;
    int p  = t - (t / HW) * HW;
    int tg = b*HW + p;                       // global pixel id

    const float2* fin = ((it & 1) ? g_pb : g_pa) + (size_t)b*PHW;
    const unsigned long long* tb = g_tab + (size_t)b*9*HW + p;

    float acc = 0.f;
    #pragma unroll
    for (int k=0;k<9;k++){
        unsigned long long v = __ldg(tb + k*HW);
        int idx  = (int)((unsigned)v & 0x7FFFFu);
        float wy = (float)((unsigned)(v >> 19) & 0xFFFu) * (1.f/4095.f);
        float wx = (float)((unsigned)(v >> 31) & 0xFFFu) * (1.f/4095.f);
        float af = (float)((long long)v >> 43) * (1.f/262144.f);
        float2 c0 = __ldg(fin + idx);
        float2 c1 = __ldg(fin + idx + PW);
        float top = c0.x + wx*(c0.y - c0.x);
        float bot = c1.x + wx*(c1.y - c1.x);
        acc = fmaf(af, top + wy*(bot - top), acc);
    }

    if (it != 17){
        float fv = __ldg(feat_fix + tg);
        float f  = (fv > 0.f) ? fv : acc;
        float2* fout = ((it & 1) ? g_pa : g_pb) + (size_t)b*PHW;
        int y = p / Ww;
        int x = p - y*Ww;
        int pidx = (y+2)*PW + (x+2);
        ((float*)(fout + pidx    ))[0] = f;   // pair[p].x
        ((float*)(fout + pidx - 1))[1] = f;   // pair[p-1].y
    } else {
        dout[tg] = acc;                       // final: raw aggregate
    }
}

extern "C" void kernel_launch(void* const* d_in, const int* in_sizes, int n_in,
                              void* d_out, int out_size)
{
    const float* feat_init  = (const float*)d_in[0];
    const float* guidance   = (const float*)d_in[1];
    const float* confidence = (const float*)d_in[2];
    const float* feat_fix   = (const float*)d_in[3];
    const float* w_oa       = (const float*)d_in[4];
    const float* b_oa       = (const float*)d_in[5];
    const float* ascale     = (const float*)d_in[6];
    float* out = (float*)d_out;

    (void)in_sizes; (void)n_in; (void)out_size;

    conv_post_kernel<<<(Bb*HW/2)/256, 256>>>(feat_init, guidance, confidence,
                                             feat_fix, w_oa, b_oa, ascale, out);
    // per-2-batch groups: each group's 42MB table stays L2-resident across its 18 iterations
    for (int b0 = 0; b0 < Bb; b0 += 2)
        for (int it = 0; it < 18; ++it)
            prop_kernel<<<(2*HW)/256, 256>>>(feat_fix, out, it, b0);
}